// round 3
// baseline (speedup 1.0000x reference)
#include <cuda_runtime.h>
#include <cuda_bf16.h>
#include <cstdint>

// Problem constants
#define BB 4096
#define TT 32
#define CC 384
#define HH 6
#define DH 64
#define LL 6
#define VV 80
#define NT (BB*TT)          // 131072 tokens
#define C4 (4*CC)           // 1536
#define QKVN (3*CC)         // 1152

// ---------------------------------------------------------------------------
// Scratch (static device globals; no runtime allocation allowed)
// ---------------------------------------------------------------------------
__device__ float g_x   [(size_t)NT * CC];      // residual stream
__device__ float g_h   [(size_t)NT * CC];      // LN output
__device__ float g_qkv [(size_t)NT * QKVN];    // fused q|k|v, col = s*384 + h*64 + d
__device__ float g_o   [(size_t)NT * CC];      // attention output (head-concat)
__device__ float g_hid [(size_t)NT * C4];      // MLP hidden
__device__ float g_wqkv[(size_t)LL * CC * QKVN]; // packed QKV weights [L][C][1152]

// ---------------------------------------------------------------------------
// Pack Wq/Wk/Wv [L,H,C,DH] -> [L][C][s*384 + h*64 + d]
// ---------------------------------------------------------------------------
__global__ void pack_qkv_kernel(const float* __restrict__ Wq,
                                const float* __restrict__ Wk,
                                const float* __restrict__ Wv)
{
    int i = blockIdx.x * blockDim.x + threadIdx.x;
    const int total = LL * CC * QKVN;
    if (i >= total) return;
    int col = i % QKVN;
    int c   = (i / QKVN) % CC;
    int l   = i / (QKVN * CC);
    int s   = col / CC;          // 0=q 1=k 2=v
    int h   = (col % CC) / DH;
    int d   = col % DH;
    const float* W = (s == 0) ? Wq : (s == 1) ? Wk : Wv;
    g_wqkv[i] = W[(((size_t)l * HH + h) * CC + c) * DH + d];
}

// ---------------------------------------------------------------------------
// Embedding: x[n,c] = tok_emb[idx[n],c] + pos_emb[n%T,c]
// ---------------------------------------------------------------------------
__global__ void embed_kernel(const int* __restrict__ idx,
                             const float* __restrict__ tok,
                             const float* __restrict__ pos)
{
    size_t i = (size_t)blockIdx.x * blockDim.x + threadIdx.x;
    if (i >= (size_t)NT * CC) return;
    int c = (int)(i % CC);
    int n = (int)(i / CC);
    int t = n % TT;
    g_x[i] = tok[(size_t)idx[n] * CC + c] + pos[(size_t)t * CC + c];
}

// ---------------------------------------------------------------------------
// LayerNorm: warp per row (C=384 = 12*32)
// ---------------------------------------------------------------------------
__global__ void ln_kernel(const float* __restrict__ x,
                          const float* __restrict__ g,
                          const float* __restrict__ b,
                          float* __restrict__ out)
{
    int row  = blockIdx.x * 8 + (threadIdx.x >> 5);
    int lane = threadIdx.x & 31;
    const float* xr = x + (size_t)row * CC;
    float vals[12];
    float s = 0.f, ss = 0.f;
#pragma unroll
    for (int i = 0; i < 12; i++) {
        float v = xr[lane + i * 32];
        vals[i] = v; s += v; ss += v * v;
    }
#pragma unroll
    for (int o = 16; o; o >>= 1) {
        s  += __shfl_xor_sync(0xffffffffu, s,  o);
        ss += __shfl_xor_sync(0xffffffffu, ss, o);
    }
    float mean = s * (1.f / CC);
    float var  = ss * (1.f / CC) - mean * mean;
    float rinv = rsqrtf(var + 1e-5f);
    float* orow = out + (size_t)row * CC;
#pragma unroll
    for (int i = 0; i < 12; i++) {
        int c = lane + i * 32;
        orow[c] = (vals[i] - mean) * rinv * g[c] + b[c];
    }
}

// ---------------------------------------------------------------------------
// SGEMM: C[M,N] = A[M,K] @ B[K,N]  (+bias, +residual, relu)
// 64x64 tile, BK=16, 256 threads, 4x4 per-thread microtile.
// M = NT (full tiles), N,K multiples of 64/16.
// ---------------------------------------------------------------------------
template<bool BIAS, bool RELU, bool RESID>
__global__ __launch_bounds__(256)
void sgemm_kernel(const float* __restrict__ A,
                  const float* __restrict__ B,
                  const float* __restrict__ bias,
                  const float* __restrict__ resid,
                  float* __restrict__ Cout,
                  int N, int K)
{
    __shared__ float As[16][68];   // [k][m], pad 68: 16B-aligned rows, reduced store conflicts
    __shared__ float Bs[16][64];   // [k][n]

    const int m0 = blockIdx.y * 64;
    const int n0 = blockIdx.x * 64;
    const int tid = threadIdx.x;
    const int tx = tid & 15;        // n subtile
    const int ty = tid >> 4;        // m subtile

    const int arow  = tid >> 2;     // 0..63
    const int acol4 = tid & 3;      // float4 along K
    const int brow  = tid >> 4;     // 0..15
    const int bcol4 = tid & 15;     // float4 along N

    const float* Aptr = A + (size_t)(m0 + arow) * K + acol4 * 4;
    const float* Bptr = B + (size_t)brow * N + n0 + bcol4 * 4;

    float acc[4][4] = {};

    for (int k0 = 0; k0 < K; k0 += 16) {
        float4 a  = *(const float4*)(Aptr + k0);
        float4 bv = *(const float4*)(Bptr + (size_t)k0 * N);
        As[acol4 * 4 + 0][arow] = a.x;
        As[acol4 * 4 + 1][arow] = a.y;
        As[acol4 * 4 + 2][arow] = a.z;
        As[acol4 * 4 + 3][arow] = a.w;
        *(float4*)&Bs[brow][bcol4 * 4] = bv;
        __syncthreads();
#pragma unroll
        for (int kk = 0; kk < 16; kk++) {
            float4 av  = *(const float4*)&As[kk][ty * 4];
            float4 bvv = *(const float4*)&Bs[kk][tx * 4];
            float ar[4] = {av.x, av.y, av.z, av.w};
            float br[4] = {bvv.x, bvv.y, bvv.z, bvv.w};
#pragma unroll
            for (int i = 0; i < 4; i++)
#pragma unroll
                for (int j = 0; j < 4; j++)
                    acc[i][j] += ar[i] * br[j];
        }
        __syncthreads();
    }

#pragma unroll
    for (int i = 0; i < 4; i++) {
        int m = m0 + ty * 4 + i;
#pragma unroll
        for (int j = 0; j < 4; j++) {
            int n = n0 + tx * 4 + j;
            float v = acc[i][j];
            if (BIAS)  v += bias[n];
            if (RESID) v += resid[(size_t)m * N + n];
            if (RELU)  v = fmaxf(v, 0.f);
            Cout[(size_t)m * N + n] = v;
        }
    }
}

// ---------------------------------------------------------------------------
// Attention: one block per (b,h). T=32, DH=64 tiles fully in smem.
// ---------------------------------------------------------------------------
__global__ __launch_bounds__(256)
void attn_kernel(const float* __restrict__ qkv, float* __restrict__ o)
{
    __shared__ float Qs[32][64], Ks[32][64], Vs[32][64], Ss[32][33];

    int bh = blockIdx.x;
    int b  = bh / HH;
    int h  = bh % HH;
    int tid = threadIdx.x;

    // load Q,K,V tiles: 32 rows x 16 float4 each
    for (int i = tid; i < 32 * 16; i += 256) {
        int t = i >> 4, d4 = i & 15;
        size_t base = (size_t)(b * TT + t) * QKVN + h * DH;
        ((float4*)Qs[t])[d4] = *((const float4*)(qkv + base) + d4);
        ((float4*)Ks[t])[d4] = *((const float4*)(qkv + base + CC) + d4);
        ((float4*)Vs[t])[d4] = *((const float4*)(qkv + base + 2 * CC) + d4);
    }
    __syncthreads();

    // S = Q K^T * scale (causal)
    for (int i = tid; i < 1024; i += 256) {
        int t = i >> 5, s = i & 31;
        float acc = -1e30f;
        if (s <= t) {
            acc = 0.f;
#pragma unroll 16
            for (int d = 0; d < 64; d++) acc += Qs[t][d] * Ks[s][d];
            acc *= 0.125f;   // 1/sqrt(64)
        }
        Ss[t][s] = acc;
    }
    __syncthreads();

    // softmax per row (thread t)
    if (tid < 32) {
        int t = tid;
        float mx = -1e30f;
        for (int s = 0; s <= t; s++) mx = fmaxf(mx, Ss[t][s]);
        float sum = 0.f;
        for (int s = 0; s <= t; s++) { float e = expf(Ss[t][s] - mx); Ss[t][s] = e; sum += e; }
        float inv = 1.f / sum;
        for (int s = 0; s <= t; s++) Ss[t][s] *= inv;
        for (int s = t + 1; s < 32; s++) Ss[t][s] = 0.f;
    }
    __syncthreads();

    // O = P V, write head-concat layout [n, h*64+d]
    for (int i = tid; i < 2048; i += 256) {
        int t = i >> 6, d = i & 63;
        float acc = 0.f;
        for (int s = 0; s <= t; s++) acc += Ss[t][s] * Vs[s][d];
        o[(size_t)(b * TT + t) * CC + h * DH + d] = acc;
    }
}

// ---------------------------------------------------------------------------
// LM head: out[n,v] = h[n,:] @ Wlm[:,v] + blm[v]   (V=80, K=384)
// block: 8 tokens x 80 vocab = 640 threads
// ---------------------------------------------------------------------------
__global__ __launch_bounds__(640)
void lmhead_kernel(const float* __restrict__ h,
                   const float* __restrict__ Wlm,
                   const float* __restrict__ blm,
                   float* __restrict__ out)
{
    __shared__ float hs[8][CC];
    int tid  = threadIdx.x;
    int row0 = blockIdx.x * 8;
    for (int i = tid; i < 8 * CC; i += 640)
        hs[i / CC][i % CC] = h[(size_t)(row0 + i / CC) * CC + (i % CC)];
    __syncthreads();

    int v = tid % VV;
    int t = tid / VV;   // 0..7
    float acc = blm[v];
#pragma unroll 4
    for (int c = 0; c < CC; c++)
        acc += hs[t][c] * Wlm[(size_t)c * VV + v];
    out[(size_t)(row0 + t) * VV + v] = acc;
}

// ---------------------------------------------------------------------------
// Host launcher
// ---------------------------------------------------------------------------
extern "C" void kernel_launch(void* const* d_in, const int* in_sizes, int n_in,
                              void* d_out, int out_size)
{
    (void)in_sizes; (void)n_in; (void)out_size;
    const int*   idx  = (const int*)  d_in[0];
    const float* tok  = (const float*)d_in[1];
    const float* pos  = (const float*)d_in[2];
    const float* ln1g = (const float*)d_in[3];
    const float* ln1b = (const float*)d_in[4];
    const float* Wq   = (const float*)d_in[5];
    const float* Wk   = (const float*)d_in[6];
    const float* Wv   = (const float*)d_in[7];
    const float* Wo   = (const float*)d_in[8];
    const float* bo   = (const float*)d_in[9];
    const float* ln2g = (const float*)d_in[10];
    const float* ln2b = (const float*)d_in[11];
    const float* W1   = (const float*)d_in[12];
    const float* b1   = (const float*)d_in[13];
    const float* W2   = (const float*)d_in[14];
    const float* b2   = (const float*)d_in[15];
    const float* lnfg = (const float*)d_in[16];
    const float* lnfb = (const float*)d_in[17];
    const float* Wlm  = (const float*)d_in[18];
    const float* blm  = (const float*)d_in[19];
    float* out = (float*)d_out;

    float *px, *ph, *pqkv, *po, *phid, *pw;
    cudaGetSymbolAddress((void**)&px,   g_x);
    cudaGetSymbolAddress((void**)&ph,   g_h);
    cudaGetSymbolAddress((void**)&pqkv, g_qkv);
    cudaGetSymbolAddress((void**)&po,   g_o);
    cudaGetSymbolAddress((void**)&phid, g_hid);
    cudaGetSymbolAddress((void**)&pw,   g_wqkv);

    // pack QKV weights
    {
        int total = LL * CC * QKVN;
        pack_qkv_kernel<<<(total + 255) / 256, 256>>>(Wq, Wk, Wv);
    }
    // embeddings
    embed_kernel<<<(int)(((size_t)NT * CC + 255) / 256), 256>>>(idx, tok, pos);

    const int MBLK = NT / 64;   // 2048
    for (int l = 0; l < LL; l++) {
        // ln1
        ln_kernel<<<NT / 8, 256>>>(px, ln1g + (size_t)l * CC, ln1b + (size_t)l * CC, ph);
        // qkv = h @ Wqkv   [NT,1152]
        sgemm_kernel<false, false, false><<<dim3(QKVN / 64, MBLK), 256>>>(
            ph, pw + (size_t)l * CC * QKVN, nullptr, nullptr, pqkv, QKVN, CC);
        // attention
        attn_kernel<<<BB * HH, 256>>>(pqkv, po);
        // x = x + o @ Wo + bo
        sgemm_kernel<true, false, true><<<dim3(CC / 64, MBLK), 256>>>(
            po, Wo + (size_t)l * CC * CC, bo + (size_t)l * CC, px, px, CC, CC);
        // ln2
        ln_kernel<<<NT / 8, 256>>>(px, ln2g + (size_t)l * CC, ln2b + (size_t)l * CC, ph);
        // hid = relu(h @ W1 + b1)   [NT,1536]
        sgemm_kernel<true, true, false><<<dim3(C4 / 64, MBLK), 256>>>(
            ph, W1 + (size_t)l * CC * C4, b1 + (size_t)l * C4, nullptr, phid, C4, CC);
        // x = x + hid @ W2 + b2
        sgemm_kernel<true, false, true><<<dim3(CC / 64, MBLK), 256>>>(
            phid, W2 + (size_t)l * C4 * CC, b2 + (size_t)l * CC, px, px, CC, C4);
    }
    // final LN + LM head
    ln_kernel<<<NT / 8, 256>>>(px, lnfg, lnfb, ph);
    lmhead_kernel<<<NT / 8, 640>>>(ph, Wlm, blm, out);
}

// round 5
// speedup vs baseline: 2.6747x; 2.6747x over previous
#include <cuda_runtime.h>
#include <cuda_bf16.h>
#include <cstdint>

// Problem constants
#define BB 4096
#define TT 32
#define CC 384
#define HH 6
#define DH 64
#define LL 6
#define VV 80
#define NT (BB*TT)          // 131072 tokens
#define C4 (4*CC)           // 1536
#define QKVN (3*CC)         // 1152

// ---------------------------------------------------------------------------
// Scratch (static device globals; no runtime allocation allowed)
// ---------------------------------------------------------------------------
__device__ float g_x   [(size_t)NT * CC];      // residual stream
__device__ float g_h   [(size_t)NT * CC];      // LN output
__device__ float g_qkv [(size_t)NT * QKVN];    // fused q|k|v
__device__ float g_o   [(size_t)NT * CC];      // attention output
__device__ float g_hid [(size_t)NT * C4];      // MLP hidden
// Transposed (K-major, [N][K]) weights
__device__ float g_wqkvT[(size_t)LL * QKVN * CC];
__device__ float g_woT  [(size_t)LL * CC * CC];
__device__ float g_w1T  [(size_t)LL * C4 * CC];
__device__ float g_w2T  [(size_t)LL * CC * C4];

// ---------------------------------------------------------------------------
// PTX helpers (sm_80+ baseline features only — no 'a'-variant instructions)
// ---------------------------------------------------------------------------
__device__ __forceinline__ uint32_t smem_u32(const void* p) {
    return (uint32_t)__cvta_generic_to_shared(p);
}
__device__ __forceinline__ void cp_async16(uint32_t s, const void* g) {
    asm volatile("cp.async.cg.shared.global [%0], [%1], 16;" :: "r"(s), "l"(g));
}
__device__ __forceinline__ void cp_commit() {
    asm volatile("cp.async.commit_group;" ::: "memory");
}
template<int N> __device__ __forceinline__ void cp_wait() {
    asm volatile("cp.async.wait_group %0;" :: "n"(N) : "memory");
}
__device__ __forceinline__ uint32_t f2tf32(float v) {
    uint32_t r;
    asm("cvt.rna.tf32.f32 %0, %1;" : "=r"(r) : "f"(v));
    return r;
}
__device__ __forceinline__ void mma_tf32(float* d, const uint32_t* a, const uint32_t* b) {
    asm volatile(
        "mma.sync.aligned.m16n8k8.row.col.f32.tf32.tf32.f32 "
        "{%0,%1,%2,%3}, {%4,%5,%6,%7}, {%8,%9}, {%0,%1,%2,%3};"
        : "+f"(d[0]), "+f"(d[1]), "+f"(d[2]), "+f"(d[3])
        : "r"(a[0]), "r"(a[1]), "r"(a[2]), "r"(a[3]), "r"(b[0]), "r"(b[1]));
}

// ---------------------------------------------------------------------------
// tf32 mma.sync GEMM: Cout[M,N] = A[M,K] @ Bt[N,K]^T  (+bias,+resid,relu)
// CTA 128x128, BK=32, 3-stage cp.async pipeline, 8 warps (2x4), warp 64x32.
// SMEM row stride 36 floats -> fragment LDS pattern (4g+t) == lane, no conflicts.
// ---------------------------------------------------------------------------
#define AS_STRIDE 36
#define STAGE_FLOATS (128*AS_STRIDE)           // 4608
#define STAGE_BYTES  (STAGE_FLOATS*4)          // 18432
#define B_BASE_F     (3*STAGE_FLOATS)          // 13824
#define DYN_SMEM     (6*STAGE_BYTES)           // 110592

#define ISSUE_STAGE(buf, ch) do {                                            \
    uint32_t bA_ = sb + (uint32_t)(buf) * STAGE_BYTES;                       \
    uint32_t bB_ = sb + (uint32_t)(B_BASE_F*4) + (uint32_t)(buf) * STAGE_BYTES; \
    _Pragma("unroll")                                                        \
    for (int i_ = 0; i_ < 4; i_++) {                                         \
        cp_async16(bA_ + offs[i_], gA[i_] + (ch) * 32);                      \
        cp_async16(bB_ + offs[i_], gB[i_] + (ch) * 32);                      \
    }                                                                        \
} while (0)

template<bool BIAS, bool RELU, bool RESID>
__global__ __launch_bounds__(256)
void mma_gemm(const float* __restrict__ A, const float* __restrict__ Bt,
              const float* __restrict__ bias, const float* __restrict__ resid,
              float* __restrict__ Cout, int N, int K)
{
    extern __shared__ float smem[];
    const uint32_t sb = smem_u32(smem);
    const int tid = threadIdx.x;
    const int wid = tid >> 5, lid = tid & 31;
    const int m0 = blockIdx.y * 128;
    const int n0 = blockIdx.x * 128;
    const int wm = (wid & 1) * 64;     // warp M offset
    const int wn = (wid >> 1) * 32;    // warp N offset
    const int g  = lid >> 2;           // groupID
    const int t  = lid & 3;            // thread-in-group

    // Load mapping: 1024 16B-chunks per tile, 4 per thread.
    uint32_t offs[4];
    const float* gA[4];
    const float* gB[4];
#pragma unroll
    for (int i = 0; i < 4; i++) {
        int q   = tid + 256 * i;
        int row = q >> 3;
        int c4  = (q & 7) * 4;
        offs[i] = (uint32_t)(row * AS_STRIDE + c4) * 4u;
        gA[i] = A  + (size_t)(m0 + row) * K + c4;
        gB[i] = Bt + (size_t)(n0 + row) * K + c4;
    }

    float acc[4][4][4] = {};
    const int nch = K >> 5;            // K/32 (>=12 always)

    // prologue: stages 0,1
    ISSUE_STAGE(0, 0); cp_commit();
    ISSUE_STAGE(1, 1); cp_commit();

    for (int c = 0; c < nch; ++c) {
        cp_wait<1>();                  // chunk c resident
        __syncthreads();               // all warps done with buffer (c-1)%3
        int cl = c + 2;
        if (cl < nch) { int buf = cl % 3; ISSUE_STAGE(buf, cl); }
        cp_commit();

        const float* As = smem + (c % 3) * STAGE_FLOATS;
        const float* Bs = smem + B_BASE_F + (c % 3) * STAGE_FLOATS;

#pragma unroll
        for (int ks = 0; ks < 4; ++ks) {
            const int kb = ks * 8;
            uint32_t a[4][4], b[4][2];
#pragma unroll
            for (int mt = 0; mt < 4; mt++) {
                const float* p = As + (wm + mt * 16 + g) * AS_STRIDE + kb + t;
                a[mt][0] = f2tf32(p[0]);
                a[mt][1] = f2tf32(p[8 * AS_STRIDE]);
                a[mt][2] = f2tf32(p[4]);
                a[mt][3] = f2tf32(p[8 * AS_STRIDE + 4]);
            }
#pragma unroll
            for (int nt = 0; nt < 4; nt++) {
                const float* p = Bs + (wn + nt * 8 + g) * AS_STRIDE + kb + t;
                b[nt][0] = f2tf32(p[0]);
                b[nt][1] = f2tf32(p[4]);
            }
#pragma unroll
            for (int mt = 0; mt < 4; mt++)
#pragma unroll
                for (int nt = 0; nt < 4; nt++)
                    mma_tf32(acc[mt][nt], a[mt], b[nt]);
        }
    }

    // epilogue straight from accumulators
#pragma unroll
    for (int mt = 0; mt < 4; mt++) {
        const size_t m1 = (size_t)m0 + wm + mt * 16 + g;
        const size_t m2 = m1 + 8;
#pragma unroll
        for (int nt = 0; nt < 4; nt++) {
            const int n = n0 + wn + nt * 8 + 2 * t;
            float2 v0 = make_float2(acc[mt][nt][0], acc[mt][nt][1]);
            float2 v1 = make_float2(acc[mt][nt][2], acc[mt][nt][3]);
            if (BIAS) {
                float2 bb = *(const float2*)(bias + n);
                v0.x += bb.x; v0.y += bb.y; v1.x += bb.x; v1.y += bb.y;
            }
            if (RESID) {
                float2 r0 = *(const float2*)(resid + m1 * N + n);
                float2 r1 = *(const float2*)(resid + m2 * N + n);
                v0.x += r0.x; v0.y += r0.y; v1.x += r1.x; v1.y += r1.y;
            }
            if (RELU) {
                v0.x = fmaxf(v0.x, 0.f); v0.y = fmaxf(v0.y, 0.f);
                v1.x = fmaxf(v1.x, 0.f); v1.y = fmaxf(v1.y, 0.f);
            }
            *(float2*)(Cout + m1 * N + n) = v0;
            *(float2*)(Cout + m2 * N + n) = v1;
        }
    }
}

// ---------------------------------------------------------------------------
// Weight packing (per call; ~42MB total, negligible)
// ---------------------------------------------------------------------------
__global__ void pack_qkvT_kernel(const float* __restrict__ Wq,
                                 const float* __restrict__ Wk,
                                 const float* __restrict__ Wv)
{
    size_t i = (size_t)blockIdx.x * blockDim.x + threadIdx.x;
    const size_t total = (size_t)LL * QKVN * CC;
    if (i >= total) return;
    int k = (int)(i % CC);
    int n = (int)((i / CC) % QKVN);
    int l = (int)(i / ((size_t)CC * QKVN));
    int s = n / CC;
    int h = (n % CC) / DH;
    int d = n % DH;
    const float* W = (s == 0) ? Wq : (s == 1) ? Wk : Wv;
    g_wqkvT[i] = W[(((size_t)l * HH + h) * CC + k) * DH + d];
}

__global__ void transposeW_kernel(const float* __restrict__ W, float* __restrict__ O,
                                  int Kd, int Nd)
{
    size_t i = (size_t)blockIdx.x * blockDim.x + threadIdx.x;
    size_t total = (size_t)LL * Kd * Nd;
    if (i >= total) return;
    int n = (int)(i % Nd);
    int k = (int)((i / Nd) % Kd);
    int l = (int)(i / ((size_t)Nd * Kd));
    O[((size_t)l * Nd + n) * Kd + k] = W[i];
}

// ---------------------------------------------------------------------------
// Embedding
// ---------------------------------------------------------------------------
__global__ void embed_kernel(const int* __restrict__ idx,
                             const float* __restrict__ tok,
                             const float* __restrict__ pos)
{
    size_t i = (size_t)blockIdx.x * blockDim.x + threadIdx.x;
    if (i >= (size_t)NT * CC) return;
    int c = (int)(i % CC);
    int n = (int)(i / CC);
    int t = n % TT;
    g_x[i] = tok[(size_t)idx[n] * CC + c] + pos[(size_t)t * CC + c];
}

// ---------------------------------------------------------------------------
// LayerNorm: warp per row
// ---------------------------------------------------------------------------
__global__ void ln_kernel(const float* __restrict__ x,
                          const float* __restrict__ g,
                          const float* __restrict__ b,
                          float* __restrict__ out)
{
    int row  = blockIdx.x * 8 + (threadIdx.x >> 5);
    int lane = threadIdx.x & 31;
    const float* xr = x + (size_t)row * CC;
    float vals[12];
    float s = 0.f, ss = 0.f;
#pragma unroll
    for (int i = 0; i < 12; i++) {
        float v = xr[lane + i * 32];
        vals[i] = v; s += v; ss += v * v;
    }
#pragma unroll
    for (int o = 16; o; o >>= 1) {
        s  += __shfl_xor_sync(0xffffffffu, s,  o);
        ss += __shfl_xor_sync(0xffffffffu, ss, o);
    }
    float mean = s * (1.f / CC);
    float var  = ss * (1.f / CC) - mean * mean;
    float rinv = rsqrtf(var + 1e-5f);
    float* orow = out + (size_t)row * CC;
#pragma unroll
    for (int i = 0; i < 12; i++) {
        int c = lane + i * 32;
        orow[c] = (vals[i] - mean) * rinv * g[c] + b[c];
    }
}

// ---------------------------------------------------------------------------
// Attention: one block per (b,h). T=32, DH=64 tiles fully in smem.
// ---------------------------------------------------------------------------
__global__ __launch_bounds__(256)
void attn_kernel(const float* __restrict__ qkv, float* __restrict__ o)
{
    __shared__ float Qs[32][64], Ks[32][64], Vs[32][64], Ss[32][33];

    int bh = blockIdx.x;
    int b  = bh / HH;
    int h  = bh % HH;
    int tid = threadIdx.x;

    for (int i = tid; i < 32 * 16; i += 256) {
        int t = i >> 4, d4 = i & 15;
        size_t base = (size_t)(b * TT + t) * QKVN + h * DH;
        ((float4*)Qs[t])[d4] = *((const float4*)(qkv + base) + d4);
        ((float4*)Ks[t])[d4] = *((const float4*)(qkv + base + CC) + d4);
        ((float4*)Vs[t])[d4] = *((const float4*)(qkv + base + 2 * CC) + d4);
    }
    __syncthreads();

    for (int i = tid; i < 1024; i += 256) {
        int t = i >> 5, s = i & 31;
        float acc = -1e30f;
        if (s <= t) {
            acc = 0.f;
#pragma unroll 16
            for (int d = 0; d < 64; d++) acc += Qs[t][d] * Ks[s][d];
            acc *= 0.125f;
        }
        Ss[t][s] = acc;
    }
    __syncthreads();

    if (tid < 32) {
        int t = tid;
        float mx = -1e30f;
        for (int s = 0; s <= t; s++) mx = fmaxf(mx, Ss[t][s]);
        float sum = 0.f;
        for (int s = 0; s <= t; s++) { float e = expf(Ss[t][s] - mx); Ss[t][s] = e; sum += e; }
        float inv = 1.f / sum;
        for (int s = 0; s <= t; s++) Ss[t][s] *= inv;
        for (int s = t + 1; s < 32; s++) Ss[t][s] = 0.f;
    }
    __syncthreads();

    for (int i = tid; i < 2048; i += 256) {
        int t = i >> 6, d = i & 63;
        float acc = 0.f;
        for (int s = 0; s <= t; s++) acc += Ss[t][s] * Vs[s][d];
        o[(size_t)(b * TT + t) * CC + h * DH + d] = acc;
    }
}

// ---------------------------------------------------------------------------
// LM head: out[n,v] = h[n,:] @ Wlm[:,v] + blm[v]   (V=80, K=384)
// ---------------------------------------------------------------------------
__global__ __launch_bounds__(640)
void lmhead_kernel(const float* __restrict__ h,
                   const float* __restrict__ Wlm,
                   const float* __restrict__ blm,
                   float* __restrict__ out)
{
    __shared__ float hs[8][CC];
    int tid  = threadIdx.x;
    int row0 = blockIdx.x * 8;
    for (int i = tid; i < 8 * CC; i += 640)
        hs[i / CC][i % CC] = h[(size_t)(row0 + i / CC) * CC + (i % CC)];
    __syncthreads();

    int v = tid % VV;
    int t = tid / VV;
    float acc = blm[v];
#pragma unroll 4
    for (int c = 0; c < CC; c++)
        acc += hs[t][c] * Wlm[(size_t)c * VV + v];
    out[(size_t)(row0 + t) * VV + v] = acc;
}

// ---------------------------------------------------------------------------
// Host launcher
// ---------------------------------------------------------------------------
extern "C" void kernel_launch(void* const* d_in, const int* in_sizes, int n_in,
                              void* d_out, int out_size)
{
    (void)in_sizes; (void)n_in; (void)out_size;
    const int*   idx  = (const int*)  d_in[0];
    const float* tok  = (const float*)d_in[1];
    const float* pos  = (const float*)d_in[2];
    const float* ln1g = (const float*)d_in[3];
    const float* ln1b = (const float*)d_in[4];
    const float* Wq   = (const float*)d_in[5];
    const float* Wk   = (const float*)d_in[6];
    const float* Wv   = (const float*)d_in[7];
    const float* Wo   = (const float*)d_in[8];
    const float* bo   = (const float*)d_in[9];
    const float* ln2g = (const float*)d_in[10];
    const float* ln2b = (const float*)d_in[11];
    const float* W1   = (const float*)d_in[12];
    const float* b1   = (const float*)d_in[13];
    const float* W2   = (const float*)d_in[14];
    const float* b2   = (const float*)d_in[15];
    const float* lnfg = (const float*)d_in[16];
    const float* lnfb = (const float*)d_in[17];
    const float* Wlm  = (const float*)d_in[18];
    const float* blm  = (const float*)d_in[19];
    float* out = (float*)d_out;

    float *px, *ph, *pqkv, *po, *phid, *pwqkvT, *pwoT, *pw1T, *pw2T;
    cudaGetSymbolAddress((void**)&px,     g_x);
    cudaGetSymbolAddress((void**)&ph,     g_h);
    cudaGetSymbolAddress((void**)&pqkv,   g_qkv);
    cudaGetSymbolAddress((void**)&po,     g_o);
    cudaGetSymbolAddress((void**)&phid,   g_hid);
    cudaGetSymbolAddress((void**)&pwqkvT, g_wqkvT);
    cudaGetSymbolAddress((void**)&pwoT,   g_woT);
    cudaGetSymbolAddress((void**)&pw1T,   g_w1T);
    cudaGetSymbolAddress((void**)&pw2T,   g_w2T);

    cudaFuncSetAttribute(mma_gemm<false, false, false>,
                         cudaFuncAttributeMaxDynamicSharedMemorySize, DYN_SMEM);
    cudaFuncSetAttribute(mma_gemm<true, false, true>,
                         cudaFuncAttributeMaxDynamicSharedMemorySize, DYN_SMEM);
    cudaFuncSetAttribute(mma_gemm<true, true, false>,
                         cudaFuncAttributeMaxDynamicSharedMemorySize, DYN_SMEM);

    // pack transposed weights
    {
        size_t t1 = (size_t)LL * QKVN * CC;
        pack_qkvT_kernel<<<(int)((t1 + 255) / 256), 256>>>(Wq, Wk, Wv);
        size_t t2 = (size_t)LL * CC * CC;
        transposeW_kernel<<<(int)((t2 + 255) / 256), 256>>>(Wo, pwoT, CC, CC);
        size_t t3 = (size_t)LL * CC * C4;
        transposeW_kernel<<<(int)((t3 + 255) / 256), 256>>>(W1, pw1T, CC, C4);
        size_t t4 = (size_t)LL * C4 * CC;
        transposeW_kernel<<<(int)((t4 + 255) / 256), 256>>>(W2, pw2T, C4, CC);
    }
    // embeddings
    embed_kernel<<<(int)(((size_t)NT * CC + 255) / 256), 256>>>(idx, tok, pos);

    const int MBLK = NT / 128;   // 1024
    for (int l = 0; l < LL; l++) {
        // ln1
        ln_kernel<<<NT / 8, 256>>>(px, ln1g + (size_t)l * CC, ln1b + (size_t)l * CC, ph);
        // qkv = h @ Wqkv   [NT,1152]
        mma_gemm<false, false, false><<<dim3(QKVN / 128, MBLK), 256, DYN_SMEM>>>(
            ph, pwqkvT + (size_t)l * QKVN * CC, nullptr, nullptr, pqkv, QKVN, CC);
        // attention
        attn_kernel<<<BB * HH, 256>>>(pqkv, po);
        // x = x + o @ Wo + bo
        mma_gemm<true, false, true><<<dim3(CC / 128, MBLK), 256, DYN_SMEM>>>(
            po, pwoT + (size_t)l * CC * CC, bo + (size_t)l * CC, px, px, CC, CC);
        // ln2
        ln_kernel<<<NT / 8, 256>>>(px, ln2g + (size_t)l * CC, ln2b + (size_t)l * CC, ph);
        // hid = relu(h @ W1 + b1)   [NT,1536]
        mma_gemm<true, true, false><<<dim3(C4 / 128, MBLK), 256, DYN_SMEM>>>(
            ph, pw1T + (size_t)l * C4 * CC, b1 + (size_t)l * C4, nullptr, phid, C4, CC);
        // x = x + hid @ W2 + b2
        mma_gemm<true, false, true><<<dim3(CC / 128, MBLK), 256, DYN_SMEM>>>(
            phid, pw2T + (size_t)l * CC * C4, b2 + (size_t)l * CC, px, px, CC, C4);
    }
    // final LN + LM head
    ln_kernel<<<NT / 8, 256>>>(px, lnfg, lnfb, ph);
    lmhead_kernel<<<NT / 8, 640>>>(ph, Wlm, blm, out);
}

// round 7
// speedup vs baseline: 2.8208x; 1.0546x over previous
#include <cuda_runtime.h>
#include <cuda_bf16.h>
#include <cuda_fp16.h>
#include <cstdint>

// Problem constants
#define BB 4096
#define TT 32
#define CC 384
#define HH 6
#define DH 64
#define LL 6
#define VV 80
#define NT (BB*TT)          // 131072 tokens
#define C4 (4*CC)           // 1536
#define QKVN (3*CC)         // 1152

// ---------------------------------------------------------------------------
// Scratch (static device globals; no runtime allocation allowed)
// ---------------------------------------------------------------------------
__device__ float g_x   [(size_t)NT * CC];      // residual stream
__device__ float g_h   [(size_t)NT * CC];      // LN output
__device__ float g_qkv [(size_t)NT * QKVN];    // fused q|k|v
__device__ float g_o   [(size_t)NT * CC];      // attention output
__device__ float g_hid [(size_t)NT * C4];      // MLP hidden
// Transposed (K-major, [N][K]) weights
__device__ float g_wqkvT[(size_t)LL * QKVN * CC];
__device__ float g_woT  [(size_t)LL * CC * CC];
__device__ float g_w1T  [(size_t)LL * C4 * CC];
__device__ float g_w2T  [(size_t)LL * CC * C4];

// ---------------------------------------------------------------------------
// PTX helpers (sm_80+ baseline features only — no 'a'-variant instructions)
// ---------------------------------------------------------------------------
__device__ __forceinline__ uint32_t smem_u32(const void* p) {
    return (uint32_t)__cvta_generic_to_shared(p);
}
__device__ __forceinline__ void cp_async16(uint32_t s, const void* g) {
    asm volatile("cp.async.cg.shared.global [%0], [%1], 16;" :: "r"(s), "l"(g));
}
__device__ __forceinline__ void cp_commit() {
    asm volatile("cp.async.commit_group;" ::: "memory");
}
template<int N> __device__ __forceinline__ void cp_wait() {
    asm volatile("cp.async.wait_group %0;" :: "n"(N) : "memory");
}
__device__ __forceinline__ uint32_t packh2(float2 v) {
    __half2 h = __float22half2_rn(v);       // .x -> low half (smaller k)
    return *(uint32_t*)&h;
}
__device__ __forceinline__ void mma_f16(float* d, const uint32_t* a, const uint32_t* b) {
    asm volatile(
        "mma.sync.aligned.m16n8k16.row.col.f32.f16.f16.f32 "
        "{%0,%1,%2,%3}, {%4,%5,%6,%7}, {%8,%9}, {%0,%1,%2,%3};"
        : "+f"(d[0]), "+f"(d[1]), "+f"(d[2]), "+f"(d[3])
        : "r"(a[0]), "r"(a[1]), "r"(a[2]), "r"(a[3]), "r"(b[0]), "r"(b[1]));
}

// ---------------------------------------------------------------------------
// fp16 mma.sync GEMM: Cout[M,N] = A[M,K] @ Bt[N,K]^T  (+bias,+resid,relu)
// CTA 128x128, BK=32, 3-stage cp.async pipeline, 8 warps (2x4), warp 64x32.
// fp32 in SMEM; operands converted to half2 in registers (same ulp as tf32).
// SMEM row stride 36 floats -> conflict-light fragment LDS.
// ---------------------------------------------------------------------------
#define AS_STRIDE 36
#define STAGE_FLOATS (128*AS_STRIDE)           // 4608
#define STAGE_BYTES  (STAGE_FLOATS*4)          // 18432
#define B_BASE_F     (3*STAGE_FLOATS)          // 13824
#define DYN_SMEM     (6*STAGE_BYTES)           // 110592

#define ISSUE_STAGE(buf, ch) do {                                            \
    uint32_t bA_ = sb + (uint32_t)(buf) * STAGE_BYTES;                       \
    uint32_t bB_ = sb + (uint32_t)(B_BASE_F*4) + (uint32_t)(buf) * STAGE_BYTES; \
    _Pragma("unroll")                                                        \
    for (int i_ = 0; i_ < 4; i_++) {                                         \
        cp_async16(bA_ + offs[i_], gA[i_] + (ch) * 32);                      \
        cp_async16(bB_ + offs[i_], gB[i_] + (ch) * 32);                      \
    }                                                                        \
} while (0)

template<bool BIAS, bool RELU, bool RESID>
__global__ __launch_bounds__(256)
void mma_gemm(const float* __restrict__ A, const float* __restrict__ Bt,
              const float* __restrict__ bias, const float* __restrict__ resid,
              float* __restrict__ Cout, int N, int K)
{
    extern __shared__ float smem[];
    const uint32_t sb = smem_u32(smem);
    const int tid = threadIdx.x;
    const int wid = tid >> 5, lid = tid & 31;
    const int m0 = blockIdx.y * 128;
    const int n0 = blockIdx.x * 128;
    const int wm = (wid & 1) * 64;     // warp M offset
    const int wn = (wid >> 1) * 32;    // warp N offset
    const int g  = lid >> 2;           // groupID
    const int t  = lid & 3;            // thread-in-group

    // Load mapping: 1024 16B-chunks per tile, 4 per thread.
    uint32_t offs[4];
    const float* gA[4];
    const float* gB[4];
#pragma unroll
    for (int i = 0; i < 4; i++) {
        int q   = tid + 256 * i;
        int row = q >> 3;
        int c4  = (q & 7) * 4;
        offs[i] = (uint32_t)(row * AS_STRIDE + c4) * 4u;
        gA[i] = A  + (size_t)(m0 + row) * K + c4;
        gB[i] = Bt + (size_t)(n0 + row) * K + c4;
    }

    float acc[4][4][4] = {};
    const int nch = K >> 5;            // K/32 (>=12 always)

    // prologue: stages 0,1
    ISSUE_STAGE(0, 0); cp_commit();
    ISSUE_STAGE(1, 1); cp_commit();

    for (int c = 0; c < nch; ++c) {
        cp_wait<1>();                  // chunk c resident
        __syncthreads();               // all warps done with buffer (c-1)%3
        int cl = c + 2;
        if (cl < nch) { int buf = cl % 3; ISSUE_STAGE(buf, cl); }
        cp_commit();

        const float* As = smem + (c % 3) * STAGE_FLOATS;
        const float* Bs = smem + B_BASE_F + (c % 3) * STAGE_FLOATS;

#pragma unroll
        for (int ks = 0; ks < 2; ++ks) {          // two k16 steps per BK=32
            const int kb = ks * 16;
            uint32_t a[4][4], b[4][2];
#pragma unroll
            for (int mt = 0; mt < 4; mt++) {
                const float* p = As + (wm + mt * 16 + g) * AS_STRIDE + kb + 2 * t;
                a[mt][0] = packh2(*(const float2*)(p));                       // row g,   k 2t,2t+1
                a[mt][1] = packh2(*(const float2*)(p + 8 * AS_STRIDE));       // row g+8, k 2t,2t+1
                a[mt][2] = packh2(*(const float2*)(p + 8));                   // row g,   k 8+2t
                a[mt][3] = packh2(*(const float2*)(p + 8 * AS_STRIDE + 8));   // row g+8, k 8+2t
            }
#pragma unroll
            for (int nt = 0; nt < 4; nt++) {
                const float* p = Bs + (wn + nt * 8 + g) * AS_STRIDE + kb + 2 * t;
                b[nt][0] = packh2(*(const float2*)(p));
                b[nt][1] = packh2(*(const float2*)(p + 8));
            }
#pragma unroll
            for (int mt = 0; mt < 4; mt++)
#pragma unroll
                for (int nt = 0; nt < 4; nt++)
                    mma_f16(acc[mt][nt], a[mt], b[nt]);
        }
    }

    // epilogue straight from accumulators
#pragma unroll
    for (int mt = 0; mt < 4; mt++) {
        const size_t m1 = (size_t)m0 + wm + mt * 16 + g;
        const size_t m2 = m1 + 8;
#pragma unroll
        for (int nt = 0; nt < 4; nt++) {
            const int n = n0 + wn + nt * 8 + 2 * t;
            float2 v0 = make_float2(acc[mt][nt][0], acc[mt][nt][1]);
            float2 v1 = make_float2(acc[mt][nt][2], acc[mt][nt][3]);
            if (BIAS) {
                float2 bb = *(const float2*)(bias + n);
                v0.x += bb.x; v0.y += bb.y; v1.x += bb.x; v1.y += bb.y;
            }
            if (RESID) {
                float2 r0 = *(const float2*)(resid + m1 * N + n);
                float2 r1 = *(const float2*)(resid + m2 * N + n);
                v0.x += r0.x; v0.y += r0.y; v1.x += r1.x; v1.y += r1.y;
            }
            if (RELU) {
                v0.x = fmaxf(v0.x, 0.f); v0.y = fmaxf(v0.y, 0.f);
                v1.x = fmaxf(v1.x, 0.f); v1.y = fmaxf(v1.y, 0.f);
            }
            *(float2*)(Cout + m1 * N + n) = v0;
            *(float2*)(Cout + m2 * N + n) = v1;
        }
    }
}

// ---------------------------------------------------------------------------
// Weight packing (per call; ~42MB total, negligible)
// ---------------------------------------------------------------------------
__global__ void pack_qkvT_kernel(const float* __restrict__ Wq,
                                 const float* __restrict__ Wk,
                                 const float* __restrict__ Wv)
{
    size_t i = (size_t)blockIdx.x * blockDim.x + threadIdx.x;
    const size_t total = (size_t)LL * QKVN * CC;
    if (i >= total) return;
    int k = (int)(i % CC);
    int n = (int)((i / CC) % QKVN);
    int l = (int)(i / ((size_t)CC * QKVN));
    int s = n / CC;
    int h = (n % CC) / DH;
    int d = n % DH;
    const float* W = (s == 0) ? Wq : (s == 1) ? Wk : Wv;
    g_wqkvT[i] = W[(((size_t)l * HH + h) * CC + k) * DH + d];
}

__global__ void transposeW_kernel(const float* __restrict__ W, float* __restrict__ O,
                                  int Kd, int Nd)
{
    size_t i = (size_t)blockIdx.x * blockDim.x + threadIdx.x;
    size_t total = (size_t)LL * Kd * Nd;
    if (i >= total) return;
    int n = (int)(i % Nd);
    int k = (int)((i / Nd) % Kd);
    int l = (int)(i / ((size_t)Nd * Kd));
    O[((size_t)l * Nd + n) * Kd + k] = W[i];
}

// ---------------------------------------------------------------------------
// Embedding
// ---------------------------------------------------------------------------
__global__ void embed_kernel(const int* __restrict__ idx,
                             const float* __restrict__ tok,
                             const float* __restrict__ pos)
{
    size_t i = (size_t)blockIdx.x * blockDim.x + threadIdx.x;
    if (i >= (size_t)NT * CC) return;
    int c = (int)(i % CC);
    int n = (int)(i / CC);
    int t = n % TT;
    g_x[i] = tok[(size_t)idx[n] * CC + c] + pos[(size_t)t * CC + c];
}

// ---------------------------------------------------------------------------
// LayerNorm: warp per row
// ---------------------------------------------------------------------------
__global__ void ln_kernel(const float* __restrict__ x,
                          const float* __restrict__ g,
                          const float* __restrict__ b,
                          float* __restrict__ out)
{
    int row  = blockIdx.x * 8 + (threadIdx.x >> 5);
    int lane = threadIdx.x & 31;
    const float* xr = x + (size_t)row * CC;
    float vals[12];
    float s = 0.f, ss = 0.f;
#pragma unroll
    for (int i = 0; i < 12; i++) {
        float v = xr[lane + i * 32];
        vals[i] = v; s += v; ss += v * v;
    }
#pragma unroll
    for (int o = 16; o; o >>= 1) {
        s  += __shfl_xor_sync(0xffffffffu, s,  o);
        ss += __shfl_xor_sync(0xffffffffu, ss, o);
    }
    float mean = s * (1.f / CC);
    float var  = ss * (1.f / CC) - mean * mean;
    float rinv = rsqrtf(var + 1e-5f);
    float* orow = out + (size_t)row * CC;
#pragma unroll
    for (int i = 0; i < 12; i++) {
        int c = lane + i * 32;
        orow[c] = (vals[i] - mean) * rinv * g[c] + b[c];
    }
}

// ---------------------------------------------------------------------------
// Attention: one block per (b,h). T=32, DH=64 tiles fully in smem.
// ---------------------------------------------------------------------------
__global__ __launch_bounds__(256)
void attn_kernel(const float* __restrict__ qkv, float* __restrict__ o)
{
    __shared__ float Qs[32][64], Ks[32][64], Vs[32][64], Ss[32][33];

    int bh = blockIdx.x;
    int b  = bh / HH;
    int h  = bh % HH;
    int tid = threadIdx.x;

    for (int i = tid; i < 32 * 16; i += 256) {
        int t = i >> 4, d4 = i & 15;
        size_t base = (size_t)(b * TT + t) * QKVN + h * DH;
        ((float4*)Qs[t])[d4] = *((const float4*)(qkv + base) + d4);
        ((float4*)Ks[t])[d4] = *((const float4*)(qkv + base + CC) + d4);
        ((float4*)Vs[t])[d4] = *((const float4*)(qkv + base + 2 * CC) + d4);
    }
    __syncthreads();

    for (int i = tid; i < 1024; i += 256) {
        int t = i >> 5, s = i & 31;
        float acc = -1e30f;
        if (s <= t) {
            acc = 0.f;
#pragma unroll 16
            for (int d = 0; d < 64; d++) acc += Qs[t][d] * Ks[s][d];
            acc *= 0.125f;
        }
        Ss[t][s] = acc;
    }
    __syncthreads();

    if (tid < 32) {
        int t = tid;
        float mx = -1e30f;
        for (int s = 0; s <= t; s++) mx = fmaxf(mx, Ss[t][s]);
        float sum = 0.f;
        for (int s = 0; s <= t; s++) { float e = expf(Ss[t][s] - mx); Ss[t][s] = e; sum += e; }
        float inv = 1.f / sum;
        for (int s = 0; s <= t; s++) Ss[t][s] *= inv;
        for (int s = t + 1; s < 32; s++) Ss[t][s] = 0.f;
    }
    __syncthreads();

    for (int i = tid; i < 2048; i += 256) {
        int t = i >> 6, d = i & 63;
        float acc = 0.f;
        for (int s = 0; s <= t; s++) acc += Ss[t][s] * Vs[s][d];
        o[(size_t)(b * TT + t) * CC + h * DH + d] = acc;
    }
}

// ---------------------------------------------------------------------------
// LM head: out[n,v] = h[n,:] @ Wlm[:,v] + blm[v]   (V=80, K=384)
// ---------------------------------------------------------------------------
__global__ __launch_bounds__(640)
void lmhead_kernel(const float* __restrict__ h,
                   const float* __restrict__ Wlm,
                   const float* __restrict__ blm,
                   float* __restrict__ out)
{
    __shared__ float hs[8][CC];
    int tid  = threadIdx.x;
    int row0 = blockIdx.x * 8;
    for (int i = tid; i < 8 * CC; i += 640)
        hs[i / CC][i % CC] = h[(size_t)(row0 + i / CC) * CC + (i % CC)];
    __syncthreads();

    int v = tid % VV;
    int t = tid / VV;
    float acc = blm[v];
#pragma unroll 4
    for (int c = 0; c < CC; c++)
        acc += hs[t][c] * Wlm[(size_t)c * VV + v];
    out[(size_t)(row0 + t) * VV + v] = acc;
}

// ---------------------------------------------------------------------------
// Host launcher
// ---------------------------------------------------------------------------
extern "C" void kernel_launch(void* const* d_in, const int* in_sizes, int n_in,
                              void* d_out, int out_size)
{
    (void)in_sizes; (void)n_in; (void)out_size;
    const int*   idx  = (const int*)  d_in[0];
    const float* tok  = (const float*)d_in[1];
    const float* pos  = (const float*)d_in[2];
    const float* ln1g = (const float*)d_in[3];
    const float* ln1b = (const float*)d_in[4];
    const float* Wq   = (const float*)d_in[5];
    const float* Wk   = (const float*)d_in[6];
    const float* Wv   = (const float*)d_in[7];
    const float* Wo   = (const float*)d_in[8];
    const float* bo   = (const float*)d_in[9];
    const float* ln2g = (const float*)d_in[10];
    const float* ln2b = (const float*)d_in[11];
    const float* W1   = (const float*)d_in[12];
    const float* b1   = (const float*)d_in[13];
    const float* W2   = (const float*)d_in[14];
    const float* b2   = (const float*)d_in[15];
    const float* lnfg = (const float*)d_in[16];
    const float* lnfb = (const float*)d_in[17];
    const float* Wlm  = (const float*)d_in[18];
    const float* blm  = (const float*)d_in[19];
    float* out = (float*)d_out;

    float *px, *ph, *pqkv, *po, *phid, *pwqkvT, *pwoT, *pw1T, *pw2T;
    cudaGetSymbolAddress((void**)&px,     g_x);
    cudaGetSymbolAddress((void**)&ph,     g_h);
    cudaGetSymbolAddress((void**)&pqkv,   g_qkv);
    cudaGetSymbolAddress((void**)&po,     g_o);
    cudaGetSymbolAddress((void**)&phid,   g_hid);
    cudaGetSymbolAddress((void**)&pwqkvT, g_wqkvT);
    cudaGetSymbolAddress((void**)&pwoT,   g_woT);
    cudaGetSymbolAddress((void**)&pw1T,   g_w1T);
    cudaGetSymbolAddress((void**)&pw2T,   g_w2T);

    cudaFuncSetAttribute(mma_gemm<false, false, false>,
                         cudaFuncAttributeMaxDynamicSharedMemorySize, DYN_SMEM);
    cudaFuncSetAttribute(mma_gemm<true, false, true>,
                         cudaFuncAttributeMaxDynamicSharedMemorySize, DYN_SMEM);
    cudaFuncSetAttribute(mma_gemm<true, true, false>,
                         cudaFuncAttributeMaxDynamicSharedMemorySize, DYN_SMEM);

    // pack transposed weights
    {
        size_t t1 = (size_t)LL * QKVN * CC;
        pack_qkvT_kernel<<<(int)((t1 + 255) / 256), 256>>>(Wq, Wk, Wv);
        size_t t2 = (size_t)LL * CC * CC;
        transposeW_kernel<<<(int)((t2 + 255) / 256), 256>>>(Wo, pwoT, CC, CC);
        size_t t3 = (size_t)LL * CC * C4;
        transposeW_kernel<<<(int)((t3 + 255) / 256), 256>>>(W1, pw1T, CC, C4);
        size_t t4 = (size_t)LL * C4 * CC;
        transposeW_kernel<<<(int)((t4 + 255) / 256), 256>>>(W2, pw2T, C4, CC);
    }
    // embeddings
    embed_kernel<<<(int)(((size_t)NT * CC + 255) / 256), 256>>>(idx, tok, pos);

    const int MBLK = NT / 128;   // 1024
    for (int l = 0; l < LL; l++) {
        // ln1
        ln_kernel<<<NT / 8, 256>>>(px, ln1g + (size_t)l * CC, ln1b + (size_t)l * CC, ph);
        // qkv = h @ Wqkv   [NT,1152]
        mma_gemm<false, false, false><<<dim3(QKVN / 128, MBLK), 256, DYN_SMEM>>>(
            ph, pwqkvT + (size_t)l * QKVN * CC, nullptr, nullptr, pqkv, QKVN, CC);
        // attention
        attn_kernel<<<BB * HH, 256>>>(pqkv, po);
        // x = x + o @ Wo + bo
        mma_gemm<true, false, true><<<dim3(CC / 128, MBLK), 256, DYN_SMEM>>>(
            po, pwoT + (size_t)l * CC * CC, bo + (size_t)l * CC, px, px, CC, CC);
        // ln2
        ln_kernel<<<NT / 8, 256>>>(px, ln2g + (size_t)l * CC, ln2b + (size_t)l * CC, ph);
        // hid = relu(h @ W1 + b1)   [NT,1536]
        mma_gemm<true, true, false><<<dim3(C4 / 128, MBLK), 256, DYN_SMEM>>>(
            ph, pw1T + (size_t)l * C4 * CC, b1 + (size_t)l * C4, nullptr, phid, C4, CC);
        // x = x + hid @ W2 + b2
        mma_gemm<true, false, true><<<dim3(CC / 128, MBLK), 256, DYN_SMEM>>>(
            phid, pw2T + (size_t)l * CC * C4, b2 + (size_t)l * CC, px, px, CC, C4);
    }
    // final LN + LM head
    ln_kernel<<<NT / 8, 256>>>(px, lnfg, lnfb, ph);
    lmhead_kernel<<<NT / 8, 640>>>(ph, Wlm, blm, out);
}

// round 8
// speedup vs baseline: 4.7621x; 1.6882x over previous
#include <cuda_runtime.h>
#include <cuda_fp16.h>
#include <cstdint>

// Problem constants
#define BB 4096
#define TT 32
#define CC 384
#define HH 6
#define DH 64
#define LL 6
#define VV 80
#define NT (BB*TT)          // 131072 tokens
#define C4 (4*CC)           // 1536
#define QKVN (3*CC)         // 1152

// ---------------------------------------------------------------------------
// Scratch (static device globals; no runtime allocation allowed)
// ---------------------------------------------------------------------------
__device__ float  g_x   [(size_t)NT * CC];      // residual stream (fp32)
__device__ float  g_qkv [(size_t)NT * QKVN];    // q|k|v (fp32, attention input)
__device__ float  g_hf  [(size_t)NT * CC];      // final LN output (fp32)
__device__ __half g_ha  [(size_t)NT * CC];      // layer LN output (half, GEMM A)
__device__ __half g_o   [(size_t)NT * CC];      // attention output (half)
__device__ __half g_hid [(size_t)NT * C4];      // MLP hidden (half)
// Transposed (K-major, [N][K]) half weights
__device__ __half g_wqkvT[(size_t)LL * QKVN * CC];
__device__ __half g_woT  [(size_t)LL * CC * CC];
__device__ __half g_w1T  [(size_t)LL * C4 * CC];
__device__ __half g_w2T  [(size_t)LL * CC * C4];

// ---------------------------------------------------------------------------
// PTX helpers (sm_80+ baseline — no 'a'-variant instructions)
// ---------------------------------------------------------------------------
__device__ __forceinline__ uint32_t smem_u32(const void* p) {
    return (uint32_t)__cvta_generic_to_shared(p);
}
__device__ __forceinline__ void cp_async16(uint32_t s, const void* g) {
    asm volatile("cp.async.cg.shared.global [%0], [%1], 16;" :: "r"(s), "l"(g));
}
__device__ __forceinline__ void cp_commit() {
    asm volatile("cp.async.commit_group;" ::: "memory");
}
template<int N> __device__ __forceinline__ void cp_wait() {
    asm volatile("cp.async.wait_group %0;" :: "n"(N) : "memory");
}
__device__ __forceinline__ void ldmat_x4(uint32_t* r, uint32_t addr) {
    asm volatile("ldmatrix.sync.aligned.m8n8.x4.shared.b16 {%0,%1,%2,%3}, [%4];"
                 : "=r"(r[0]), "=r"(r[1]), "=r"(r[2]), "=r"(r[3]) : "r"(addr));
}
__device__ __forceinline__ void mma_f16(float* d, const uint32_t* a, uint32_t b0, uint32_t b1) {
    asm volatile(
        "mma.sync.aligned.m16n8k16.row.col.f32.f16.f16.f32 "
        "{%0,%1,%2,%3}, {%4,%5,%6,%7}, {%8,%9}, {%0,%1,%2,%3};"
        : "+f"(d[0]), "+f"(d[1]), "+f"(d[2]), "+f"(d[3])
        : "r"(a[0]), "r"(a[1]), "r"(a[2]), "r"(a[3]), "r"(b0), "r"(b1));
}

// ---------------------------------------------------------------------------
// fp16 ldmatrix GEMM: Cout[M,N] = A[M,K] @ Bt[N,K]^T  (+bias,+resid,relu)
// A,B half in gmem/smem. CTA 128x128, BK=64, 3-stage cp.async, 8 warps 2x4.
// SMEM: 128B rows (64 half), 16B-chunk XOR swizzle -> conflict-free ldmatrix.
// ---------------------------------------------------------------------------
#define A_SZ 16384                 // 128 rows * 128B
#define STAGE_BYTES 32768          // A + B
#define NSTG 3
#define DYN_SMEM (NSTG*STAGE_BYTES)  // 98304

#define ISSUE_STAGE(buf, ch) do {                                            \
    uint32_t bA_ = sb + (uint32_t)(buf) * STAGE_BYTES;                       \
    uint32_t bB_ = bA_ + A_SZ;                                               \
    _Pragma("unroll")                                                        \
    for (int i_ = 0; i_ < 4; i_++) {                                         \
        cp_async16(bA_ + offs[i_], gA[i_] + (size_t)(ch) * 64);              \
        cp_async16(bB_ + offs[i_], gB[i_] + (size_t)(ch) * 64);              \
    }                                                                        \
} while (0)

template<bool BIAS, bool RELU, bool RESID, bool OUTH>
__global__ __launch_bounds__(256)
void mma_gemm(const __half* __restrict__ A, const __half* __restrict__ Bt,
              const float* __restrict__ bias, const float* __restrict__ resid,
              void* __restrict__ CoutV, int N, int K)
{
    extern __shared__ char smem[];
    const uint32_t sb = smem_u32(smem);
    const int tid = threadIdx.x;
    const int wid = tid >> 5, lid = tid & 31;
    const int m0 = blockIdx.y * 128;
    const int n0 = blockIdx.x * 128;
    const int wm = (wid & 1) * 64;     // warp M offset
    const int wn = (wid >> 1) * 32;    // warp N offset
    const int g  = lid >> 2;           // groupID
    const int t  = lid & 3;            // thread-in-group

    // cp.async mapping: 1024 16B chunks per (A|B) tile, 4 per thread each.
    uint32_t offs[4];
    const __half* gA[4];
    const __half* gB[4];
#pragma unroll
    for (int i = 0; i < 4; i++) {
        int q   = tid + 256 * i;
        int row = q >> 3;              // 0..127
        int c   = q & 7;               // 16B chunk within 128B row
        offs[i] = (uint32_t)(row * 128 + ((c ^ (row & 7)) << 4));
        gA[i] = A  + (size_t)(m0 + row) * K + c * 8;
        gB[i] = Bt + (size_t)(n0 + row) * K + c * 8;
    }

    // ldmatrix per-lane addressing
    const int lrow = lid & 15;         // row within 16-row tile
    const int lsel = lid >> 4;         // 0: k chunk lo, 1: hi
    const int lx   = lrow & 7;         // row swizzle key
    const uint32_t aBase = sb + (uint32_t)((wm + lrow) * 128);
    const uint32_t bBase = sb + A_SZ + (uint32_t)((wn + lrow) * 128);

    float acc[4][4][4] = {};
    const int nch = K >> 6;            // K/64 (6 or 24)

    ISSUE_STAGE(0, 0); cp_commit();
    ISSUE_STAGE(1, 1); cp_commit();

    for (int c = 0; c < nch; ++c) {
        cp_wait<1>();
        __syncthreads();
        int cl = c + 2;
        if (cl < nch) { ISSUE_STAGE(cl % NSTG, cl); }
        cp_commit();

        const uint32_t stg = (uint32_t)((c % NSTG) * STAGE_BYTES);

#pragma unroll
        for (int ks = 0; ks < 4; ++ks) {
            const uint32_t sw = (uint32_t)(((ks * 2 + lsel) ^ lx) << 4);
            uint32_t a[4][4], b[2][4];
#pragma unroll
            for (int mt = 0; mt < 4; mt++)
                ldmat_x4(a[mt], aBase + stg + (uint32_t)(mt * 2048) + sw);
            ldmat_x4(b[0], bBase + stg + sw);
            ldmat_x4(b[1], bBase + stg + 2048u + sw);
#pragma unroll
            for (int mt = 0; mt < 4; mt++)
#pragma unroll
                for (int nt = 0; nt < 4; nt++)
                    mma_f16(acc[mt][nt], a[mt],
                            b[nt >> 1][nt & 1], b[nt >> 1][2 + (nt & 1)]);
        }
    }

    // epilogue
#pragma unroll
    for (int mt = 0; mt < 4; mt++) {
        const size_t m1 = (size_t)m0 + wm + mt * 16 + g;
        const size_t m2 = m1 + 8;
#pragma unroll
        for (int nt = 0; nt < 4; nt++) {
            const int n = n0 + wn + nt * 8 + 2 * t;
            float2 v0 = make_float2(acc[mt][nt][0], acc[mt][nt][1]);
            float2 v1 = make_float2(acc[mt][nt][2], acc[mt][nt][3]);
            if (BIAS) {
                float2 bb = *(const float2*)(bias + n);
                v0.x += bb.x; v0.y += bb.y; v1.x += bb.x; v1.y += bb.y;
            }
            if (RESID) {
                float2 r0 = *(const float2*)(resid + m1 * N + n);
                float2 r1 = *(const float2*)(resid + m2 * N + n);
                v0.x += r0.x; v0.y += r0.y; v1.x += r1.x; v1.y += r1.y;
            }
            if (RELU) {
                v0.x = fmaxf(v0.x, 0.f); v0.y = fmaxf(v0.y, 0.f);
                v1.x = fmaxf(v1.x, 0.f); v1.y = fmaxf(v1.y, 0.f);
            }
            if (OUTH) {
                __half* Cout = (__half*)CoutV;
                *(__half2*)(Cout + m1 * N + n) = __float22half2_rn(v0);
                *(__half2*)(Cout + m2 * N + n) = __float22half2_rn(v1);
            } else {
                float* Cout = (float*)CoutV;
                *(float2*)(Cout + m1 * N + n) = v0;
                *(float2*)(Cout + m2 * N + n) = v1;
            }
        }
    }
}

// ---------------------------------------------------------------------------
// Weight packing (per call; small)
// ---------------------------------------------------------------------------
__global__ void pack_qkvT_kernel(const float* __restrict__ Wq,
                                 const float* __restrict__ Wk,
                                 const float* __restrict__ Wv)
{
    size_t i = (size_t)blockIdx.x * blockDim.x + threadIdx.x;
    const size_t total = (size_t)LL * QKVN * CC;
    if (i >= total) return;
    int k = (int)(i % CC);
    int n = (int)((i / CC) % QKVN);
    int l = (int)(i / ((size_t)CC * QKVN));
    int s = n / CC;
    int h = (n % CC) / DH;
    int d = n % DH;
    const float* W = (s == 0) ? Wq : (s == 1) ? Wk : Wv;
    g_wqkvT[i] = __float2half(W[(((size_t)l * HH + h) * CC + k) * DH + d]);
}

__global__ void transposeW_kernel(const float* __restrict__ W, __half* __restrict__ O,
                                  int Kd, int Nd)
{
    size_t i = (size_t)blockIdx.x * blockDim.x + threadIdx.x;
    size_t total = (size_t)LL * Kd * Nd;
    if (i >= total) return;
    int n = (int)(i % Nd);
    int k = (int)((i / Nd) % Kd);
    int l = (int)(i / ((size_t)Nd * Kd));
    O[((size_t)l * Nd + n) * Kd + k] = __float2half(W[i]);
}

// ---------------------------------------------------------------------------
// Embedding
// ---------------------------------------------------------------------------
__global__ void embed_kernel(const int* __restrict__ idx,
                             const float* __restrict__ tok,
                             const float* __restrict__ pos)
{
    size_t i = (size_t)blockIdx.x * blockDim.x + threadIdx.x;
    if (i >= (size_t)NT * CC) return;
    int c = (int)(i % CC);
    int n = (int)(i / CC);
    int t = n % TT;
    g_x[i] = tok[(size_t)idx[n] * CC + c] + pos[(size_t)t * CC + c];
}

// ---------------------------------------------------------------------------
// LayerNorm: warp per row; half or float output
// ---------------------------------------------------------------------------
template<bool OUTH>
__global__ void ln_kernel(const float* __restrict__ x,
                          const float* __restrict__ g,
                          const float* __restrict__ b,
                          void* __restrict__ outV)
{
    int row  = blockIdx.x * 8 + (threadIdx.x >> 5);
    int lane = threadIdx.x & 31;
    const float* xr = x + (size_t)row * CC;
    float vals[12];
    float s = 0.f, ss = 0.f;
#pragma unroll
    for (int i = 0; i < 12; i++) {
        float v = xr[lane + i * 32];
        vals[i] = v; s += v; ss += v * v;
    }
#pragma unroll
    for (int o = 16; o; o >>= 1) {
        s  += __shfl_xor_sync(0xffffffffu, s,  o);
        ss += __shfl_xor_sync(0xffffffffu, ss, o);
    }
    float mean = s * (1.f / CC);
    float var  = ss * (1.f / CC) - mean * mean;
    float rinv = rsqrtf(var + 1e-5f);
#pragma unroll
    for (int i = 0; i < 12; i++) {
        int c = lane + i * 32;
        float v = (vals[i] - mean) * rinv * g[c] + b[c];
        if (OUTH) ((__half*)outV)[(size_t)row * CC + c] = __float2half(v);
        else      ((float*)outV)[(size_t)row * CC + c] = v;
    }
}

// ---------------------------------------------------------------------------
// Attention: one block per (b,h). fp32 math, half output.
// ---------------------------------------------------------------------------
__global__ __launch_bounds__(256)
void attn_kernel(const float* __restrict__ qkv, __half* __restrict__ o)
{
    __shared__ float Qs[32][64], Ks[32][64], Vs[32][64], Ss[32][33];

    int bh = blockIdx.x;
    int b  = bh / HH;
    int h  = bh % HH;
    int tid = threadIdx.x;

    for (int i = tid; i < 32 * 16; i += 256) {
        int t = i >> 4, d4 = i & 15;
        size_t base = (size_t)(b * TT + t) * QKVN + h * DH;
        ((float4*)Qs[t])[d4] = *((const float4*)(qkv + base) + d4);
        ((float4*)Ks[t])[d4] = *((const float4*)(qkv + base + CC) + d4);
        ((float4*)Vs[t])[d4] = *((const float4*)(qkv + base + 2 * CC) + d4);
    }
    __syncthreads();

    for (int i = tid; i < 1024; i += 256) {
        int t = i >> 5, s = i & 31;
        float acc = -1e30f;
        if (s <= t) {
            acc = 0.f;
#pragma unroll 16
            for (int d = 0; d < 64; d++) acc += Qs[t][d] * Ks[s][d];
            acc *= 0.125f;
        }
        Ss[t][s] = acc;
    }
    __syncthreads();

    if (tid < 32) {
        int t = tid;
        float mx = -1e30f;
        for (int s = 0; s <= t; s++) mx = fmaxf(mx, Ss[t][s]);
        float sum = 0.f;
        for (int s = 0; s <= t; s++) { float e = expf(Ss[t][s] - mx); Ss[t][s] = e; sum += e; }
        float inv = 1.f / sum;
        for (int s = 0; s <= t; s++) Ss[t][s] *= inv;
        for (int s = t + 1; s < 32; s++) Ss[t][s] = 0.f;
    }
    __syncthreads();

    for (int i = tid; i < 2048; i += 256) {
        int t = i >> 6, d = i & 63;
        float acc = 0.f;
        for (int s = 0; s <= t; s++) acc += Ss[t][s] * Vs[s][d];
        o[(size_t)(b * TT + t) * CC + h * DH + d] = __float2half(acc);
    }
}

// ---------------------------------------------------------------------------
// LM head: out[n,v] = h[n,:] @ Wlm[:,v] + blm[v]   (V=80, K=384), fp32
// ---------------------------------------------------------------------------
__global__ __launch_bounds__(640)
void lmhead_kernel(const float* __restrict__ h,
                   const float* __restrict__ Wlm,
                   const float* __restrict__ blm,
                   float* __restrict__ out)
{
    __shared__ float hs[8][CC];
    int tid  = threadIdx.x;
    int row0 = blockIdx.x * 8;
    for (int i = tid; i < 8 * CC; i += 640)
        hs[i / CC][i % CC] = h[(size_t)(row0 + i / CC) * CC + (i % CC)];
    __syncthreads();

    int v = tid % VV;
    int t = tid / VV;
    float acc = blm[v];
#pragma unroll 4
    for (int c = 0; c < CC; c++)
        acc += hs[t][c] * Wlm[(size_t)c * VV + v];
    out[(size_t)(row0 + t) * VV + v] = acc;
}

// ---------------------------------------------------------------------------
// Host launcher
// ---------------------------------------------------------------------------
extern "C" void kernel_launch(void* const* d_in, const int* in_sizes, int n_in,
                              void* d_out, int out_size)
{
    (void)in_sizes; (void)n_in; (void)out_size;
    const int*   idx  = (const int*)  d_in[0];
    const float* tok  = (const float*)d_in[1];
    const float* pos  = (const float*)d_in[2];
    const float* ln1g = (const float*)d_in[3];
    const float* ln1b = (const float*)d_in[4];
    const float* Wq   = (const float*)d_in[5];
    const float* Wk   = (const float*)d_in[6];
    const float* Wv   = (const float*)d_in[7];
    const float* Wo   = (const float*)d_in[8];
    const float* bo   = (const float*)d_in[9];
    const float* ln2g = (const float*)d_in[10];
    const float* ln2b = (const float*)d_in[11];
    const float* W1   = (const float*)d_in[12];
    const float* b1   = (const float*)d_in[13];
    const float* W2   = (const float*)d_in[14];
    const float* b2   = (const float*)d_in[15];
    const float* lnfg = (const float*)d_in[16];
    const float* lnfb = (const float*)d_in[17];
    const float* Wlm  = (const float*)d_in[18];
    const float* blm  = (const float*)d_in[19];
    float* out = (float*)d_out;

    float *px, *pqkv, *phf;
    __half *pha, *po, *phid, *pwqkvT, *pwoT, *pw1T, *pw2T;
    cudaGetSymbolAddress((void**)&px,     g_x);
    cudaGetSymbolAddress((void**)&pqkv,   g_qkv);
    cudaGetSymbolAddress((void**)&phf,    g_hf);
    cudaGetSymbolAddress((void**)&pha,    g_ha);
    cudaGetSymbolAddress((void**)&po,     g_o);
    cudaGetSymbolAddress((void**)&phid,   g_hid);
    cudaGetSymbolAddress((void**)&pwqkvT, g_wqkvT);
    cudaGetSymbolAddress((void**)&pwoT,   g_woT);
    cudaGetSymbolAddress((void**)&pw1T,   g_w1T);
    cudaGetSymbolAddress((void**)&pw2T,   g_w2T);

    cudaFuncSetAttribute(mma_gemm<false, false, false, false>,
                         cudaFuncAttributeMaxDynamicSharedMemorySize, DYN_SMEM);
    cudaFuncSetAttribute(mma_gemm<true, false, true, false>,
                         cudaFuncAttributeMaxDynamicSharedMemorySize, DYN_SMEM);
    cudaFuncSetAttribute(mma_gemm<true, true, false, true>,
                         cudaFuncAttributeMaxDynamicSharedMemorySize, DYN_SMEM);

    // pack half weights
    {
        size_t t1 = (size_t)LL * QKVN * CC;
        pack_qkvT_kernel<<<(int)((t1 + 255) / 256), 256>>>(Wq, Wk, Wv);
        size_t t2 = (size_t)LL * CC * CC;
        transposeW_kernel<<<(int)((t2 + 255) / 256), 256>>>(Wo, pwoT, CC, CC);
        size_t t3 = (size_t)LL * CC * C4;
        transposeW_kernel<<<(int)((t3 + 255) / 256), 256>>>(W1, pw1T, CC, C4);
        size_t t4 = (size_t)LL * C4 * CC;
        transposeW_kernel<<<(int)((t4 + 255) / 256), 256>>>(W2, pw2T, C4, CC);
    }
    // embeddings
    embed_kernel<<<(int)(((size_t)NT * CC + 255) / 256), 256>>>(idx, tok, pos);

    const int MBLK = NT / 128;   // 1024
    for (int l = 0; l < LL; l++) {
        // ln1 -> half
        ln_kernel<true><<<NT / 8, 256>>>(px, ln1g + (size_t)l * CC, ln1b + (size_t)l * CC, pha);
        // qkv = h @ Wqkv   [NT,1152] fp32 out
        mma_gemm<false, false, false, false><<<dim3(QKVN / 128, MBLK), 256, DYN_SMEM>>>(
            pha, pwqkvT + (size_t)l * QKVN * CC, nullptr, nullptr, pqkv, QKVN, CC);
        // attention (fp32 in, half out)
        attn_kernel<<<BB * HH, 256>>>(pqkv, po);
        // x = x + o @ Wo + bo  (fp32 out)
        mma_gemm<true, false, true, false><<<dim3(CC / 128, MBLK), 256, DYN_SMEM>>>(
            po, pwoT + (size_t)l * CC * CC, bo + (size_t)l * CC, px, px, CC, CC);
        // ln2 -> half
        ln_kernel<true><<<NT / 8, 256>>>(px, ln2g + (size_t)l * CC, ln2b + (size_t)l * CC, pha);
        // hid = relu(h @ W1 + b1)   [NT,1536] half out
        mma_gemm<true, true, false, true><<<dim3(C4 / 128, MBLK), 256, DYN_SMEM>>>(
            pha, pw1T + (size_t)l * C4 * CC, b1 + (size_t)l * C4, nullptr, phid, C4, CC);
        // x = x + hid @ W2 + b2  (fp32 out)
        mma_gemm<true, false, true, false><<<dim3(CC / 128, MBLK), 256, DYN_SMEM>>>(
            phid, pw2T + (size_t)l * CC * C4, b2 + (size_t)l * CC, px, px, CC, C4);
    }
    // final LN (fp32) + LM head
    ln_kernel<false><<<NT / 8, 256>>>(px, lnfg, lnfb, phf);
    lmhead_kernel<<<NT / 8, 640>>>(phf, Wlm, blm, out);
}